// round 8
// baseline (speedup 1.0000x reference)
#include <cuda_runtime.h>
#include <cstddef>

// Problem constants (fixed by the reference):
//   B_PAIRS=2048 pairs, each pair = 44 ligand nodes + 300 protein nodes (stride 344)
//   Only the ligand segment sums (even segments) feed the MLP.
//   MLP: 128 ->256 relu -> 128 relu -> 64 relu -> 1
#define B_PAIRS 2048
#define LIG     44
#define STRIDE  344
#define F_IN    128
#define N0      256
#define N1      128
#define N2      64
#define RTILE   4          // pairs per MLP block -> grid 512
#define THREADS 256

typedef unsigned long long u64;

// 1 MB scratch for the per-pair feature sums.
__device__ float g_xs[B_PAIRS * F_IN];

// ---------------- packed fp32x2 helpers (sm_103a FFMA2) --------------------
#define PACK_F32X2(d, lo, hi) \
    asm("mov.b64 %0, {%1, %2};" : "=l"(d) : "f"(lo), "f"(hi))
#define UNPACK_F32X2(lo, hi, v) \
    asm("mov.b64 {%0, %1}, %2;" : "=f"(lo), "=f"(hi) : "l"(v))
#define FMA_F32X2(d, a, b, c) \
    asm("fma.rn.f32x2 %0, %1, %2, %3;" : "=l"(d) : "l"(a), "l"(b), "l"(c))
#define ADD_F32X2(d, a, b) \
    asm("add.rn.f32x2 %0, %1, %2;" : "=l"(d) : "l"(a), "l"(b))

// ============================================================================
// Kernel A: ligand segment sum. One block per pair (hot set is L2-resident).
// ============================================================================
__global__ void __launch_bounds__(THREADS)
seg_sum_kernel(const float* __restrict__ features)
{
    __shared__ float4 part[8][32];
    const int tid  = threadIdx.x;
    const int pair = blockIdx.x;
    const int c4   = tid & 31;
    const int g    = tid >> 5;

    const float4* src = reinterpret_cast<const float4*>(features)
                      + (size_t)pair * STRIDE * (F_IN / 4) + c4;
    float4 acc = make_float4(0.f, 0.f, 0.f, 0.f);
#pragma unroll
    for (int r = g; r < LIG; r += 8) {
        float4 v = __ldcs(src + (size_t)r * (F_IN / 4));
        acc.x += v.x; acc.y += v.y; acc.z += v.z; acc.w += v.w;
    }
    part[g][c4] = acc;
    __syncthreads();

    if (tid < 32) {
        float4 s = part[0][tid];
#pragma unroll
        for (int gg = 1; gg < 8; ++gg) {
            float4 v = part[gg][tid];
            s.x += v.x; s.y += v.y; s.z += v.z; s.w += v.w;
        }
        reinterpret_cast<float4*>(g_xs)[pair * (F_IN / 4) + tid] = s;
    }
}

// ============================================================================
// Kernel B: 4-layer MLP, RTILE=4 rows, grid=512, 256 threads.
// Main loops: 128 threads, thread = 8 cols (L0/L1) or 4 cols (L2) x 4 rows
// over a k-slice. Dup-activation LDS + packed-pair weight LDG, zero packing.
// L1-cycle cost: (2R + C) cyc per R*C*32 lane-MACs -> 0.5 for C=8.
// All-thread transposed-pbuf reductions (conflict-free STS/LDS.64).
// ============================================================================
__global__ void __launch_bounds__(THREADS)
mlp_kernel(const float* __restrict__ W0, const float* __restrict__ b0,
           const float* __restrict__ W1, const float* __restrict__ b1,
           const float* __restrict__ W2, const float* __restrict__ b2,
           const float* __restrict__ Wout, const float* __restrict__ bout,
           float* __restrict__ out)
{
    __shared__ __align__(16) u64  xsD[F_IN][RTILE];   // 4 KB dup activations
    __shared__ __align__(16) u64  h0D[N0][RTILE];     // 8 KB
    __shared__ __align__(16) u64  h1D[N1][RTILE];     // 4 KB
    __shared__ __align__(16) float h2T[N2][RTILE];    // 1 KB
    __shared__ __align__(16) u64  pbuf[2048];         // 16 KB partials

    const int tid = threadIdx.x;
    const int p0  = blockIdx.x * RTILE;

    // Load 4 summed rows, duplicate-pack into SMEM.
    if (tid < 128) {
        const int pp = tid & 3;
        const int c4 = tid >> 2;                 // 0..31
        float4 v = reinterpret_cast<const float4*>(g_xs)
                       [(size_t)(p0 + pp) * (F_IN / 4) + c4];
        u64 d0, d1, d2, d3;
        PACK_F32X2(d0, v.x, v.x); PACK_F32X2(d1, v.y, v.y);
        PACK_F32X2(d2, v.z, v.z); PACK_F32X2(d3, v.w, v.w);
        xsD[c4 * 4 + 0][pp] = d0;
        xsD[c4 * 4 + 1][pp] = d1;
        xsD[c4 * 4 + 2][pp] = d2;
        xsD[c4 * 4 + 3][pp] = d3;
    }
    __syncthreads();

    // ======== Layer 0: [4,128]@[128,256]+b relu ============================
    // Main: 128 thr = 32 ct (8 cols) x 4 kq (32 k). acc[i], i = r*4+cp.
    if (tid < 128) {
        const int ct = tid & 31;
        const int kq = tid >> 5;
        u64 acc[16];
#pragma unroll
        for (int i = 0; i < 16; ++i) acc[i] = 0ull;
        const float* Wp = W0 + (size_t)(kq * 32) * N0 + 8 * ct;
#pragma unroll 8
        for (int kk = 0; kk < 32; ++kk) {
            const float* wrow = Wp + (size_t)kk * N0;
            ulonglong2 w01 = *reinterpret_cast<const ulonglong2*>(wrow);
            ulonglong2 w23 = *reinterpret_cast<const ulonglong2*>(wrow + 4);
            const u64* ap = &xsD[kq * 32 + kk][0];
            ulonglong2 a01 = *reinterpret_cast<const ulonglong2*>(ap);
            ulonglong2 a23 = *reinterpret_cast<const ulonglong2*>(ap + 2);
#define L0_ROW(r, av) \
            FMA_F32X2(acc[(r)*4+0], av, w01.x, acc[(r)*4+0]); \
            FMA_F32X2(acc[(r)*4+1], av, w01.y, acc[(r)*4+1]); \
            FMA_F32X2(acc[(r)*4+2], av, w23.x, acc[(r)*4+2]); \
            FMA_F32X2(acc[(r)*4+3], av, w23.y, acc[(r)*4+3]);
            L0_ROW(0, a01.x) L0_ROW(1, a01.y) L0_ROW(2, a23.x) L0_ROW(3, a23.y)
#undef L0_ROW
        }
        // pbuf[(kq*16 + i)*32 + ct]
#pragma unroll
        for (int i = 0; i < 16; ++i)
            pbuf[(kq * 16 + i) * 32 + ct] = acc[i];
    }
    __syncthreads();
    // Reduce: 512 elements, 2 per thread. e -> (i = e>>5, job = e&31).
    {
#pragma unroll
        for (int ee = 0; ee < 2; ++ee) {
            const int e   = tid + ee * 256;
            const int i   = e >> 5;
            const int job = e & 31;
            const int r   = i >> 2;
            const int cp  = i & 3;
            u64 s = pbuf[i * 32 + job];
#pragma unroll
            for (int q = 1; q < 4; ++q) {
                u64 t2 = pbuf[(q * 16 + i) * 32 + job];
                ADD_F32X2(s, s, t2);
            }
            const int c0 = job * 8 + cp * 2;
            u64 bb = *reinterpret_cast<const u64*>(b0 + c0);
            ADD_F32X2(s, s, bb);
            float v0, v1; UNPACK_F32X2(v0, v1, s);
            v0 = fmaxf(v0, 0.f); v1 = fmaxf(v1, 0.f);
            u64 d0, d1; PACK_F32X2(d0, v0, v0); PACK_F32X2(d1, v1, v1);
            h0D[c0    ][r] = d0;
            h0D[c0 + 1][r] = d1;
        }
    }
    __syncthreads();

    // ======== Layer 1: [4,256]@[256,128]+b relu ============================
    // Main: 128 thr = 16 ct (8 cols) x 8 kq (32 k).
    if (tid < 128) {
        const int ct = tid & 15;
        const int kq = tid >> 4;
        u64 acc[16];
#pragma unroll
        for (int i = 0; i < 16; ++i) acc[i] = 0ull;
        const float* Wp = W1 + (size_t)(kq * 32) * N1 + 8 * ct;
#pragma unroll 8
        for (int kk = 0; kk < 32; ++kk) {
            const float* wrow = Wp + (size_t)kk * N1;
            ulonglong2 w01 = *reinterpret_cast<const ulonglong2*>(wrow);
            ulonglong2 w23 = *reinterpret_cast<const ulonglong2*>(wrow + 4);
            const u64* ap = &h0D[kq * 32 + kk][0];
            ulonglong2 a01 = *reinterpret_cast<const ulonglong2*>(ap);
            ulonglong2 a23 = *reinterpret_cast<const ulonglong2*>(ap + 2);
#define L1_ROW(r, av) \
            FMA_F32X2(acc[(r)*4+0], av, w01.x, acc[(r)*4+0]); \
            FMA_F32X2(acc[(r)*4+1], av, w01.y, acc[(r)*4+1]); \
            FMA_F32X2(acc[(r)*4+2], av, w23.x, acc[(r)*4+2]); \
            FMA_F32X2(acc[(r)*4+3], av, w23.y, acc[(r)*4+3]);
            L1_ROW(0, a01.x) L1_ROW(1, a01.y) L1_ROW(2, a23.x) L1_ROW(3, a23.y)
#undef L1_ROW
        }
        // pbuf[(kq*16 + i)*16 + ct]
#pragma unroll
        for (int i = 0; i < 16; ++i)
            pbuf[(kq * 16 + i) * 16 + ct] = acc[i];
    }
    __syncthreads();
    // Reduce: 256 elements, 1 per thread. e -> (i = e>>4, job = e&15).
    {
        const int e   = tid;
        const int i   = e >> 4;
        const int job = e & 15;
        const int r   = i >> 2;
        const int cp  = i & 3;
        u64 s = pbuf[i * 16 + job];
#pragma unroll
        for (int q = 1; q < 8; ++q) {
            u64 t2 = pbuf[(q * 16 + i) * 16 + job];
            ADD_F32X2(s, s, t2);
        }
        const int c0 = job * 8 + cp * 2;
        u64 bb = *reinterpret_cast<const u64*>(b1 + c0);
        ADD_F32X2(s, s, bb);
        float v0, v1; UNPACK_F32X2(v0, v1, s);
        v0 = fmaxf(v0, 0.f); v1 = fmaxf(v1, 0.f);
        u64 d0, d1; PACK_F32X2(d0, v0, v0); PACK_F32X2(d1, v1, v1);
        h1D[c0    ][r] = d0;
        h1D[c0 + 1][r] = d1;
    }
    __syncthreads();

    // ======== Layer 2: [4,128]@[128,64]+b relu =============================
    // Main: 128 thr = 16 ct (4 cols) x 8 kq (16 k). acc[i], i = r*2+cp.
    if (tid < 128) {
        const int ct = tid & 15;
        const int kq = tid >> 4;
        u64 acc[8];
#pragma unroll
        for (int i = 0; i < 8; ++i) acc[i] = 0ull;
        const float* Wp = W2 + (size_t)(kq * 16) * N2 + 4 * ct;
#pragma unroll
        for (int kk = 0; kk < 16; ++kk) {
            ulonglong2 w01 = *reinterpret_cast<const ulonglong2*>(
                                 Wp + (size_t)kk * N2);
            const u64* ap = &h1D[kq * 16 + kk][0];
            ulonglong2 a01 = *reinterpret_cast<const ulonglong2*>(ap);
            ulonglong2 a23 = *reinterpret_cast<const ulonglong2*>(ap + 2);
            FMA_F32X2(acc[0], a01.x, w01.x, acc[0]);
            FMA_F32X2(acc[1], a01.x, w01.y, acc[1]);
            FMA_F32X2(acc[2], a01.y, w01.x, acc[2]);
            FMA_F32X2(acc[3], a01.y, w01.y, acc[3]);
            FMA_F32X2(acc[4], a23.x, w01.x, acc[4]);
            FMA_F32X2(acc[5], a23.x, w01.y, acc[5]);
            FMA_F32X2(acc[6], a23.y, w01.x, acc[6]);
            FMA_F32X2(acc[7], a23.y, w01.y, acc[7]);
        }
        // pbuf[(kq*8 + i)*16 + ct]
#pragma unroll
        for (int i = 0; i < 8; ++i)
            pbuf[(kq * 8 + i) * 16 + ct] = acc[i];
    }
    __syncthreads();
    // Reduce: 128 elements on 128 threads. e -> (i = e>>4, job = e&15).
    if (tid < 128) {
        const int e   = tid;
        const int i   = e >> 4;
        const int job = e & 15;
        const int r   = i >> 1;
        const int cp  = i & 1;
        u64 s = pbuf[i * 16 + job];
#pragma unroll
        for (int q = 1; q < 8; ++q) {
            u64 t2 = pbuf[(q * 8 + i) * 16 + job];
            ADD_F32X2(s, s, t2);
        }
        const int c0 = job * 4 + cp * 2;
        u64 bb = *reinterpret_cast<const u64*>(b2 + c0);
        ADD_F32X2(s, s, bb);
        float v0, v1; UNPACK_F32X2(v0, v1, s);
        h2T[c0    ][r] = fmaxf(v0, 0.f);
        h2T[c0 + 1][r] = fmaxf(v1, 0.f);
    }
    __syncthreads();

    // ======== Output: [4,64]@[64,1]+b =======================================
    {
        const int warp = tid >> 5;
        const int lane = tid & 31;
        if (warp < RTILE) {
            float s = h2T[2 * lane][warp]     * Wout[2 * lane]
                    + h2T[2 * lane + 1][warp] * Wout[2 * lane + 1];
#pragma unroll
            for (int o = 16; o > 0; o >>= 1)
                s += __shfl_down_sync(0xffffffffu, s, o);
            if (lane == 0)
                out[p0 + warp] = s + bout[0];
        }
    }
}

// d_in order (metadata): [0] batch_num_nodes (unused), [1] features,
// [2] W0, [3] b0, [4] W1, [5] b1, [6] W2, [7] b2, [8] Wout, [9] bout.
extern "C" void kernel_launch(void* const* d_in, const int* in_sizes, int n_in,
                              void* d_out, int out_size)
{
    const float* features = (const float*)d_in[1];
    const float* W0   = (const float*)d_in[2];
    const float* b0   = (const float*)d_in[3];
    const float* W1   = (const float*)d_in[4];
    const float* b1   = (const float*)d_in[5];
    const float* W2   = (const float*)d_in[6];
    const float* b2   = (const float*)d_in[7];
    const float* Wout = (const float*)d_in[8];
    const float* bout = (const float*)d_in[9];
    float* out = (float*)d_out;

    seg_sum_kernel<<<B_PAIRS, THREADS>>>(features);
    mlp_kernel<<<B_PAIRS / RTILE, THREADS>>>(W0, b0, W1, b1, W2, b2,
                                             Wout, bout, out);
}

// round 9
// speedup vs baseline: 1.3922x; 1.3922x over previous
#include <cuda_runtime.h>
#include <cstddef>

// Problem constants (fixed by the reference):
//   B_PAIRS=2048 pairs, each pair = 44 ligand nodes + 300 protein nodes (stride 344)
//   Only the ligand segment sums (even segments) feed the MLP.
//   MLP: 128 ->256 relu -> 128 relu -> 64 relu -> 1
#define B_PAIRS 2048
#define LIG     44
#define STRIDE  344
#define F_IN    128
#define N0      256
#define N1      128
#define N2      64
#define RTILE   8          // pairs per MLP block -> grid 256
#define THREADS 256

typedef unsigned long long u64;

// 1 MB scratch for the per-pair feature sums.
__device__ float g_xs[B_PAIRS * F_IN];

// ---------------- packed fp32x2 helpers (sm_103a FFMA2) --------------------
#define PACK_F32X2(d, lo, hi) \
    asm("mov.b64 %0, {%1, %2};" : "=l"(d) : "f"(lo), "f"(hi))
#define UNPACK_F32X2(lo, hi, v) \
    asm("mov.b64 {%0, %1}, %2;" : "=f"(lo), "=f"(hi) : "l"(v))
#define FMA_F32X2(d, a, b, c) \
    asm("fma.rn.f32x2 %0, %1, %2, %3;" : "=l"(d) : "l"(a), "l"(b), "l"(c))
#define ADD_F32X2(d, a, b) \
    asm("add.rn.f32x2 %0, %1, %2;" : "=l"(d) : "l"(a), "l"(b))

// ============================================================================
// Kernel A: ligand segment sum. One block per pair; DRAM-bound (46 MB once).
// ============================================================================
__global__ void __launch_bounds__(THREADS)
seg_sum_kernel(const float* __restrict__ features)
{
    __shared__ float4 part[8][32];
    const int tid  = threadIdx.x;
    const int pair = blockIdx.x;
    const int c4   = tid & 31;
    const int g    = tid >> 5;

    const float4* src = reinterpret_cast<const float4*>(features)
                      + (size_t)pair * STRIDE * (F_IN / 4) + c4;
    float4 acc = make_float4(0.f, 0.f, 0.f, 0.f);
#pragma unroll
    for (int r = g; r < LIG; r += 8) {
        float4 v = __ldcs(src + (size_t)r * (F_IN / 4));
        acc.x += v.x; acc.y += v.y; acc.z += v.z; acc.w += v.w;
    }
    part[g][c4] = acc;
    __syncthreads();

    if (tid < 32) {
        float4 s = part[0][tid];
#pragma unroll
        for (int gg = 1; gg < 8; ++gg) {
            float4 v = part[gg][tid];
            s.x += v.x; s.y += v.y; s.z += v.z; s.w += v.w;
        }
        reinterpret_cast<float4*>(g_xs)[pair * (F_IN / 4) + tid] = s;
    }
}

// ============================================================================
// Kernel B: 4-layer MLP, RTILE=8 rows per block, grid=256, 256 threads.
// Job shape everywhere: 1 column-pair (packed weights via LDG.64) x 8 rows
// (dup-activation LDS.128 broadcasts) over a k-slice -> 8 u64 accumulators.
// Per warp-iter: 1 LDG.64 + 4 LDS.128 + 8 FFMA2 = 0.375 L1-cyc / 32 MACs.
// Weight matrices are read exactly once per block (k-splits partition k).
// ============================================================================
__global__ void __launch_bounds__(THREADS)
mlp_kernel(const float* __restrict__ W0, const float* __restrict__ b0,
           const float* __restrict__ W1, const float* __restrict__ b1,
           const float* __restrict__ W2, const float* __restrict__ b2,
           const float* __restrict__ Wout, const float* __restrict__ bout,
           float* __restrict__ out)
{
    __shared__ __align__(16) u64  xsD[F_IN][RTILE];   //  8 KB dup activations
    __shared__ __align__(16) u64  h0D[N0][RTILE];     // 16 KB
    __shared__ __align__(16) u64  h1D[N1][RTILE];     //  8 KB
    __shared__ __align__(16) float h2T[N2][RTILE];    //  2 KB
    __shared__ __align__(16) u64  pbuf[7 * 32 * 8];   // 14 KB partials

    const int tid = threadIdx.x;
    const int p0  = blockIdx.x * RTILE;

    // Load 8 summed rows, duplicate-pack into SMEM. (pp = tid&7, c4 = tid>>3)
    {
        const int pp = tid & 7;
        const int c4 = tid >> 3;                 // 0..31
        float4 v = reinterpret_cast<const float4*>(g_xs)
                       [(size_t)(p0 + pp) * (F_IN / 4) + c4];
        u64 d0, d1, d2, d3;
        PACK_F32X2(d0, v.x, v.x); PACK_F32X2(d1, v.y, v.y);
        PACK_F32X2(d2, v.z, v.z); PACK_F32X2(d3, v.w, v.w);
        xsD[c4 * 4 + 0][pp] = d0;
        xsD[c4 * 4 + 1][pp] = d1;
        xsD[c4 * 4 + 2][pp] = d2;
        xsD[c4 * 4 + 3][pp] = d3;
    }
    __syncthreads();

    // ======== Layer 0: [8,128]@[128,256]+b relu | 128 cp x 2 kq x 64 ========
    {
        const int ct = tid & 127;                // colpair: cols 2ct, 2ct+1
        const int kq = tid >> 7;                 // 0/1, 64 k each
        u64 acc[8];
#pragma unroll
        for (int r = 0; r < 8; ++r) acc[r] = 0ull;
        const float* Wp = W0 + (size_t)(kq * 64) * N0 + 2 * ct;
#pragma unroll 8
        for (int kk = 0; kk < 64; ++kk) {
            u64 w = *reinterpret_cast<const u64*>(Wp + (size_t)kk * N0);
            const u64* ap = &xsD[kq * 64 + kk][0];
            ulonglong2 a01 = *reinterpret_cast<const ulonglong2*>(ap);
            ulonglong2 a23 = *reinterpret_cast<const ulonglong2*>(ap + 2);
            ulonglong2 a45 = *reinterpret_cast<const ulonglong2*>(ap + 4);
            ulonglong2 a67 = *reinterpret_cast<const ulonglong2*>(ap + 6);
            FMA_F32X2(acc[0], a01.x, w, acc[0]);
            FMA_F32X2(acc[1], a01.y, w, acc[1]);
            FMA_F32X2(acc[2], a23.x, w, acc[2]);
            FMA_F32X2(acc[3], a23.y, w, acc[3]);
            FMA_F32X2(acc[4], a45.x, w, acc[4]);
            FMA_F32X2(acc[5], a45.y, w, acc[5]);
            FMA_F32X2(acc[6], a67.x, w, acc[6]);
            FMA_F32X2(acc[7], a67.y, w, acc[7]);
        }
        if (kq == 1) {
            u64* dst = &pbuf[ct * 8];
#pragma unroll
            for (int r = 0; r < 8; r += 2)
                *reinterpret_cast<ulonglong2*>(dst + r) =
                    make_ulonglong2(acc[r], acc[r + 1]);
        }
        __syncthreads();
        if (kq == 0) {
            const u64* q = &pbuf[ct * 8];
            u64 bb = *reinterpret_cast<const u64*>(b0 + 2 * ct);
#pragma unroll
            for (int r = 0; r < 8; r += 2) {
                ulonglong2 qq = *reinterpret_cast<const ulonglong2*>(q + r);
                ADD_F32X2(acc[r],     acc[r],     qq.x);
                ADD_F32X2(acc[r + 1], acc[r + 1], qq.y);
            }
#pragma unroll
            for (int r = 0; r < 8; ++r) {
                ADD_F32X2(acc[r], acc[r], bb);
                float v0, v1; UNPACK_F32X2(v0, v1, acc[r]);
                v0 = fmaxf(v0, 0.f); v1 = fmaxf(v1, 0.f);
                u64 d0, d1; PACK_F32X2(d0, v0, v0); PACK_F32X2(d1, v1, v1);
                h0D[2 * ct    ][r] = d0;
                h0D[2 * ct + 1][r] = d1;
            }
        }
    }
    __syncthreads();

    // ======== Layer 1: [8,256]@[256,128]+b relu | 64 cp x 4 kq x 64 =========
    {
        const int ct = tid & 63;                 // colpair
        const int kq = tid >> 6;                 // 0..3, 64 k each
        u64 acc[8];
#pragma unroll
        for (int r = 0; r < 8; ++r) acc[r] = 0ull;
        const float* Wp = W1 + (size_t)(kq * 64) * N1 + 2 * ct;
#pragma unroll 8
        for (int kk = 0; kk < 64; ++kk) {
            u64 w = *reinterpret_cast<const u64*>(Wp + (size_t)kk * N1);
            const u64* ap = &h0D[kq * 64 + kk][0];
            ulonglong2 a01 = *reinterpret_cast<const ulonglong2*>(ap);
            ulonglong2 a23 = *reinterpret_cast<const ulonglong2*>(ap + 2);
            ulonglong2 a45 = *reinterpret_cast<const ulonglong2*>(ap + 4);
            ulonglong2 a67 = *reinterpret_cast<const ulonglong2*>(ap + 6);
            FMA_F32X2(acc[0], a01.x, w, acc[0]);
            FMA_F32X2(acc[1], a01.y, w, acc[1]);
            FMA_F32X2(acc[2], a23.x, w, acc[2]);
            FMA_F32X2(acc[3], a23.y, w, acc[3]);
            FMA_F32X2(acc[4], a45.x, w, acc[4]);
            FMA_F32X2(acc[5], a45.y, w, acc[5]);
            FMA_F32X2(acc[6], a67.x, w, acc[6]);
            FMA_F32X2(acc[7], a67.y, w, acc[7]);
        }
        if (kq > 0) {
            u64* dst = &pbuf[((kq - 1) * 64 + ct) * 8];
#pragma unroll
            for (int r = 0; r < 8; r += 2)
                *reinterpret_cast<ulonglong2*>(dst + r) =
                    make_ulonglong2(acc[r], acc[r + 1]);
        }
        __syncthreads();
        if (kq == 0) {
#pragma unroll
            for (int t = 0; t < 3; ++t) {
                const u64* q = &pbuf[(t * 64 + ct) * 8];
#pragma unroll
                for (int r = 0; r < 8; r += 2) {
                    ulonglong2 qq = *reinterpret_cast<const ulonglong2*>(q + r);
                    ADD_F32X2(acc[r],     acc[r],     qq.x);
                    ADD_F32X2(acc[r + 1], acc[r + 1], qq.y);
                }
            }
            u64 bb = *reinterpret_cast<const u64*>(b1 + 2 * ct);
#pragma unroll
            for (int r = 0; r < 8; ++r) {
                ADD_F32X2(acc[r], acc[r], bb);
                float v0, v1; UNPACK_F32X2(v0, v1, acc[r]);
                v0 = fmaxf(v0, 0.f); v1 = fmaxf(v1, 0.f);
                u64 d0, d1; PACK_F32X2(d0, v0, v0); PACK_F32X2(d1, v1, v1);
                h1D[2 * ct    ][r] = d0;
                h1D[2 * ct + 1][r] = d1;
            }
        }
    }
    __syncthreads();

    // ======== Layer 2: [8,128]@[128,64]+b relu | 32 cp x 8 kq x 16 ==========
    {
        const int ct = tid & 31;                 // colpair
        const int kq = tid >> 5;                 // 0..7, 16 k each
        u64 acc[8];
#pragma unroll
        for (int r = 0; r < 8; ++r) acc[r] = 0ull;
        const float* Wp = W2 + (size_t)(kq * 16) * N2 + 2 * ct;
#pragma unroll
        for (int kk = 0; kk < 16; ++kk) {
            u64 w = *reinterpret_cast<const u64*>(Wp + (size_t)kk * N2);
            const u64* ap = &h1D[kq * 16 + kk][0];
            ulonglong2 a01 = *reinterpret_cast<const ulonglong2*>(ap);
            ulonglong2 a23 = *reinterpret_cast<const ulonglong2*>(ap + 2);
            ulonglong2 a45 = *reinterpret_cast<const ulonglong2*>(ap + 4);
            ulonglong2 a67 = *reinterpret_cast<const ulonglong2*>(ap + 6);
            FMA_F32X2(acc[0], a01.x, w, acc[0]);
            FMA_F32X2(acc[1], a01.y, w, acc[1]);
            FMA_F32X2(acc[2], a23.x, w, acc[2]);
            FMA_F32X2(acc[3], a23.y, w, acc[3]);
            FMA_F32X2(acc[4], a45.x, w, acc[4]);
            FMA_F32X2(acc[5], a45.y, w, acc[5]);
            FMA_F32X2(acc[6], a67.x, w, acc[6]);
            FMA_F32X2(acc[7], a67.y, w, acc[7]);
        }
        if (kq > 0) {
            u64* dst = &pbuf[((kq - 1) * 32 + ct) * 8];
#pragma unroll
            for (int r = 0; r < 8; r += 2)
                *reinterpret_cast<ulonglong2*>(dst + r) =
                    make_ulonglong2(acc[r], acc[r + 1]);
        }
        __syncthreads();
        if (kq == 0) {
#pragma unroll
            for (int t = 0; t < 7; ++t) {
                const u64* q = &pbuf[(t * 32 + ct) * 8];
#pragma unroll
                for (int r = 0; r < 8; r += 2) {
                    ulonglong2 qq = *reinterpret_cast<const ulonglong2*>(q + r);
                    ADD_F32X2(acc[r],     acc[r],     qq.x);
                    ADD_F32X2(acc[r + 1], acc[r + 1], qq.y);
                }
            }
            u64 bb = *reinterpret_cast<const u64*>(b2 + 2 * ct);
#pragma unroll
            for (int r = 0; r < 8; ++r) {
                ADD_F32X2(acc[r], acc[r], bb);
                float v0, v1; UNPACK_F32X2(v0, v1, acc[r]);
                h2T[2 * ct    ][r] = fmaxf(v0, 0.f);
                h2T[2 * ct + 1][r] = fmaxf(v1, 0.f);
            }
        }
    }
    __syncthreads();

    // ======== Output: [8,64]@[64,1]+b  (8 warps = 8 rows) ===================
    {
        const int warp = tid >> 5;
        const int lane = tid & 31;
        float s = h2T[2 * lane][warp]     * Wout[2 * lane]
                + h2T[2 * lane + 1][warp] * Wout[2 * lane + 1];
#pragma unroll
        for (int o = 16; o > 0; o >>= 1)
            s += __shfl_down_sync(0xffffffffu, s, o);
        if (lane == 0)
            out[p0 + warp] = s + bout[0];
    }
}

// d_in order (metadata): [0] batch_num_nodes (unused), [1] features,
// [2] W0, [3] b0, [4] W1, [5] b1, [6] W2, [7] b2, [8] Wout, [9] bout.
extern "C" void kernel_launch(void* const* d_in, const int* in_sizes, int n_in,
                              void* d_out, int out_size)
{
    const float* features = (const float*)d_in[1];
    const float* W0   = (const float*)d_in[2];
    const float* b0   = (const float*)d_in[3];
    const float* W1   = (const float*)d_in[4];
    const float* b1   = (const float*)d_in[5];
    const float* W2   = (const float*)d_in[6];
    const float* b2   = (const float*)d_in[7];
    const float* Wout = (const float*)d_in[8];
    const float* bout = (const float*)d_in[9];
    float* out = (float*)d_out;

    seg_sum_kernel<<<B_PAIRS, THREADS>>>(features);
    mlp_kernel<<<B_PAIRS / RTILE, THREADS>>>(W0, b0, W1, b1, W2, b2,
                                             Wout, bout, out);
}